// round 1
// baseline (speedup 1.0000x reference)
#include <cuda_runtime.h>
#include <cstdint>
#include <cstddef>

#define Nn 100000
#define En 500000
#define HID 128
#define NH 8
#define DKv 16
#define DFFv 512

// ---------------- scratch (device globals; allocation-free) ----------------
__device__ float g_k[2][(size_t)Nn * HID];
__device__ float g_q[2][(size_t)Nn * HID];
__device__ float g_v[2][(size_t)Nn * HID];
__device__ float g_kp[(size_t)Nn * HID];
__device__ float g_vp[(size_t)Nn * HID];
__device__ float g_s[(size_t)En * NH];
__device__ unsigned g_m[(size_t)Nn * NH];
__device__ float g_z[(size_t)Nn * NH];
__device__ float g_t[2][(size_t)Nn * HID];
__device__ float g_x[(size_t)Nn * HID];
__device__ float g_ff[(size_t)Nn * DFFv];
__device__ int g_idx[6][En];
__device__ int g_is64;

// ---------------- helpers ----------------
__device__ __forceinline__ unsigned fenc(float x) {
    unsigned u = __float_as_uint(x);
    return (u >> 31) ? ~u : (u | 0x80000000u);
}
__device__ __forceinline__ float fdec(unsigned v) {
    return __uint_as_float((v >> 31) ? (v & 0x7fffffffu) : ~v);
}

__global__ void fill_f32(float* p, float v, int n) {
    int i = blockIdx.x * blockDim.x + threadIdx.x;
    if (i < n) p[i] = v;
}
__global__ void fill_u32(unsigned* p, unsigned v, int n) {
    int i = blockIdx.x * blockDim.x + threadIdx.x;
    if (i < n) p[i] = v;
}

// Detect whether index buffers are int64 (odd 32-bit words == 0) or int32.
__global__ void detect_kernel(const unsigned* __restrict__ p) {
    if (blockIdx.x == 0 && threadIdx.x == 0) {
        int any = 0;
        for (int i = 1; i < 2048; i += 2) any |= (p[i] != 0u);
        g_is64 = !any;
    }
}
__global__ void conv_idx_kernel(const void* __restrict__ in, int which, int n) {
    int i = blockIdx.x * blockDim.x + threadIdx.x;
    if (i >= n) return;
    int v = g_is64 ? (int)((const long long*)in)[i] : ((const int*)in)[i];
    g_idx[which][i] = v;
}

// ---------------- SGEMM: C[M,Nc] = act( (reluA?relu(A):A)[M,K] @ B[K,Nc] + bias + res ) ----------------
#define BM 128
#define BN 128
#define BKs 8
__global__ __launch_bounds__(256) void sgemm_kernel(
    const float* __restrict__ A, const float* __restrict__ B,
    const float* __restrict__ bias, const float* __restrict__ res,
    float* __restrict__ C, int M, int K, int Nc, int reluA, int reluOut)
{
    __shared__ float As[BKs][BM];
    __shared__ float Bs[BKs][BN];
    int tid = threadIdx.x;
    int rowTile = blockIdx.y * BM;
    int colTile = blockIdx.x * BN;
    int tr = tid >> 4;          // 0..15
    int tc = tid & 15;          // 0..15
    int aRow = tid >> 1;        // 0..127
    int aCol = (tid & 1) * 4;   // 0 or 4
    int bRow = tid >> 5;        // 0..7
    int bCol = (tid & 31) * 4;  // 0..124

    float acc[8][8];
#pragma unroll
    for (int i = 0; i < 8; i++)
#pragma unroll
        for (int j = 0; j < 8; j++) acc[i][j] = 0.f;

    for (int k0 = 0; k0 < K; k0 += BKs) {
        float4 av = make_float4(0.f, 0.f, 0.f, 0.f);
        int gr = rowTile + aRow;
        if (gr < M) av = *reinterpret_cast<const float4*>(A + (size_t)gr * K + k0 + aCol);
        if (reluA) {
            av.x = fmaxf(av.x, 0.f); av.y = fmaxf(av.y, 0.f);
            av.z = fmaxf(av.z, 0.f); av.w = fmaxf(av.w, 0.f);
        }
        As[aCol + 0][aRow] = av.x;
        As[aCol + 1][aRow] = av.y;
        As[aCol + 2][aRow] = av.z;
        As[aCol + 3][aRow] = av.w;

        float4 bv = *reinterpret_cast<const float4*>(B + (size_t)(k0 + bRow) * Nc + colTile + bCol);
        *reinterpret_cast<float4*>(&Bs[bRow][bCol]) = bv;
        __syncthreads();

#pragma unroll
        for (int kk = 0; kk < BKs; kk++) {
            float ra[8], rb[8];
#pragma unroll
            for (int i = 0; i < 8; i++) ra[i] = As[kk][tr * 8 + i];
#pragma unroll
            for (int j = 0; j < 8; j++) rb[j] = Bs[kk][tc * 8 + j];
#pragma unroll
            for (int i = 0; i < 8; i++)
#pragma unroll
                for (int j = 0; j < 8; j++) acc[i][j] += ra[i] * rb[j];
        }
        __syncthreads();
    }

    float bvals[8];
#pragma unroll
    for (int j = 0; j < 8; j++) bvals[j] = bias[colTile + tc * 8 + j];

#pragma unroll
    for (int i = 0; i < 8; i++) {
        int gr = rowTile + tr * 8 + i;
        if (gr >= M) continue;
        size_t off = (size_t)gr * Nc + colTile + tc * 8;
#pragma unroll
        for (int j = 0; j < 8; j++) {
            float v = acc[i][j] + bvals[j];
            if (res) v += res[off + j];
            if (reluOut) v = fmaxf(v, 0.f);
            C[off + j] = v;
        }
    }
}

// ---------------- per-head 16x16 transform: Y[n,h,:] = X[n,h,:] @ A[h] ----------------
__global__ __launch_bounds__(256) void head_transform_kernel(
    const float* __restrict__ X, const float* __restrict__ A8,
    float* __restrict__ Y, int M)
{
    __shared__ float sA[NH * DKv * DKv];   // 2048
    __shared__ float sX[16 * HID];         // 2048
    int tid = threadIdx.x;
    for (int i = tid; i < NH * DKv * DKv; i += 256) sA[i] = A8[i];
    int base = blockIdx.x * 16;
    for (int i = tid; i < 16 * HID; i += 256) {
        int node = base + (i >> 7);
        sX[i] = (node < M) ? X[(size_t)node * HID + (i & 127)] : 0.f;
    }
    __syncthreads();
#pragma unroll
    for (int o = tid; o < 16 * HID; o += 256) {
        int nl = o >> 7;
        int c = o & 127;
        int h = c >> 4;
        int j = c & 15;
        const float* xr = &sX[nl * HID + h * DKv];
        const float* ar = &sA[h * DKv * DKv + j];
        float acc = 0.f;
#pragma unroll
        for (int i2 = 0; i2 < DKv; i2++) acc += xr[i2] * ar[i2 * DKv];
        int node = base + nl;
        if (node < M) Y[(size_t)node * HID + c] = acc;
    }
}

// ---------------- edge score + segment max ----------------
__global__ __launch_bounds__(256) void score_kernel(
    const float* __restrict__ Q, const float* __restrict__ KP,
    const int* __restrict__ src, const int* __restrict__ dst,
    const float* __restrict__ pri, float* __restrict__ S,
    unsigned* __restrict__ Mx, int Ecnt)
{
    int warp = (blockIdx.x * blockDim.x + threadIdx.x) >> 5;
    int lane = threadIdx.x & 31;
    if (warp >= Ecnt) return;
    int s = src[warp], d = dst[warp];
    float4 qv = *reinterpret_cast<const float4*>(Q + (size_t)d * HID + lane * 4);
    float4 kv = *reinterpret_cast<const float4*>(KP + (size_t)s * HID + lane * 4);
    float p = qv.x * kv.x + qv.y * kv.y + qv.z * kv.z + qv.w * kv.w;
    p += __shfl_xor_sync(0xffffffffu, p, 1);
    p += __shfl_xor_sync(0xffffffffu, p, 2);
    int h = lane >> 2;
    float sc = p * pri[h] * 0.25f;   // / sqrt(DK=16)
    if ((lane & 3) == 0) {
        S[(size_t)warp * NH + h] = sc;
        atomicMax(&Mx[(size_t)d * NH + h], fenc(sc));
    }
}

// ---------------- exp + segment sum ----------------
__global__ __launch_bounds__(256) void expz_kernel(
    float* __restrict__ S, const unsigned* __restrict__ Mx,
    float* __restrict__ Z, const int* __restrict__ dst, int Ecnt)
{
    int idx = blockIdx.x * blockDim.x + threadIdx.x;
    if (idx >= Ecnt * NH) return;
    int e = idx >> 3;
    int h = idx & 7;
    int d = dst[e];
    float m = fdec(Mx[(size_t)d * NH + h]);
    float ev = expf(S[idx] - m);
    S[idx] = ev;
    atomicAdd(&Z[(size_t)d * NH + h], ev);
}

// ---------------- weighted scatter aggregation ----------------
__global__ __launch_bounds__(256) void agg_kernel(
    const float* __restrict__ VP, const float* __restrict__ S,
    const float* __restrict__ Z, const int* __restrict__ src,
    const int* __restrict__ dst, float* __restrict__ T, int Ecnt)
{
    int warp = (blockIdx.x * blockDim.x + threadIdx.x) >> 5;
    int lane = threadIdx.x & 31;
    if (warp >= Ecnt) return;
    int s = src[warp], d = dst[warp];
    int h = lane >> 2;
    float a = S[(size_t)warp * NH + h] / Z[(size_t)d * NH + h];
    float4 v = *reinterpret_cast<const float4*>(VP + (size_t)s * HID + lane * 4);
    float* tp = T + (size_t)d * HID + lane * 4;
    atomicAdd(tp + 0, v.x * a);
    atomicAdd(tp + 1, v.y * a);
    atomicAdd(tp + 2, v.z * a);
    atomicAdd(tp + 3, v.w * a);
}

// ---------------- LayerNorm over 128 (warp per row, in-place) ----------------
__global__ __launch_bounds__(256) void ln_kernel(
    float* __restrict__ X, const float* __restrict__ gamma,
    const float* __restrict__ beta, int M)
{
    int warp = (blockIdx.x * blockDim.x + threadIdx.x) >> 5;
    int lane = threadIdx.x & 31;
    if (warp >= M) return;
    float4 v = *reinterpret_cast<float4*>(X + (size_t)warp * HID + lane * 4);
    float sum = v.x + v.y + v.z + v.w;
    float sq = v.x * v.x + v.y * v.y + v.z * v.z + v.w * v.w;
#pragma unroll
    for (int o = 16; o > 0; o >>= 1) {
        sum += __shfl_xor_sync(0xffffffffu, sum, o);
        sq += __shfl_xor_sync(0xffffffffu, sq, o);
    }
    float mu = sum * (1.f / 128.f);
    float var = sq * (1.f / 128.f) - mu * mu;
    float inv = rsqrtf(var + 1e-5f);
    float4 g = *reinterpret_cast<const float4*>(gamma + lane * 4);
    float4 b = *reinterpret_cast<const float4*>(beta + lane * 4);
    v.x = (v.x - mu) * inv * g.x + b.x;
    v.y = (v.y - mu) * inv * g.y + b.y;
    v.z = (v.z - mu) * inv * g.z + b.z;
    v.w = (v.w - mu) * inv * g.w + b.w;
    *reinterpret_cast<float4*>(X + (size_t)warp * HID + lane * 4) = v;
}

// ---------------- host ----------------
static void sgemm(const float* A, const float* B, const float* bias, const float* res,
                  float* C, int M, int K, int Nc, int reluA, int reluOut)
{
    dim3 grid(Nc / BN, (M + BM - 1) / BM);
    sgemm_kernel<<<grid, 256>>>(A, B, bias, res, C, M, K, Nc, reluA, reluOut);
}

template <typename T>
static T* symaddr(const void* sym) {
    void* p = nullptr;
    cudaGetSymbolAddress(&p, sym);
    return (T*)p;
}

extern "C" void kernel_launch(void* const* d_in, const int* in_sizes, int n_in,
                              void* d_out, int out_size)
{
    const float* h_a  = (const float*)d_in[0];
    const float* h_b  = (const float*)d_in[1];
    const float* Wk   = (const float*)d_in[2];
    const float* bk   = (const float*)d_in[3];
    const float* Wq   = (const float*)d_in[4];
    const float* bq   = (const float*)d_in[5];
    const float* Wv   = (const float*)d_in[6];
    const float* bv   = (const float*)d_in[7];
    const float* Wa   = (const float*)d_in[8];
    const float* ba   = (const float*)d_in[9];
    const float* gam  = (const float*)d_in[10];
    const float* bet  = (const float*)d_in[11];
    const float* W1   = (const float*)d_in[12];
    const float* b1   = (const float*)d_in[13];
    const float* W2   = (const float*)d_in[14];
    const float* b2   = (const float*)d_in[15];
    const float* pri  = (const float*)d_in[16];
    const float* ratt = (const float*)d_in[17];
    const float* rmsg = (const float*)d_in[18];

    int M = in_sizes[0] / HID;      // N nodes per type
    int Ec[3] = { in_sizes[19], in_sizes[21], in_sizes[23] };
    float* out = (float*)d_out;

    float* k0 = symaddr<float>(&g_k);  float* k1 = k0 + (size_t)Nn * HID;
    float* q0 = symaddr<float>(&g_q);  float* q1 = q0 + (size_t)Nn * HID;
    float* v0 = symaddr<float>(&g_v);  float* v1 = v0 + (size_t)Nn * HID;
    float* kp = symaddr<float>(&g_kp);
    float* vp = symaddr<float>(&g_vp);
    float* S  = symaddr<float>(&g_s);
    unsigned* Mx = symaddr<unsigned>(&g_m);
    float* Z  = symaddr<float>(&g_z);
    float* t0 = symaddr<float>(&g_t);  float* t1 = t0 + (size_t)Nn * HID;
    float* X  = symaddr<float>(&g_x);
    float* FF = symaddr<float>(&g_ff);
    int* gidx = symaddr<int>(&g_idx);

    // ---- index dtype normalization (device-side detection) ----
    detect_kernel<<<1, 32>>>((const unsigned*)d_in[19]);
    for (int i = 0; i < 6; i++) {
        int e = Ec[i / 2];
        conv_idx_kernel<<<(e + 255) / 256, 256>>>(d_in[19 + i], i, e);
    }

    // ---- zero aggregation targets ----
    {
        int n = 2 * Nn * HID;
        fill_f32<<<(n + 255) / 256, 256>>>(t0, 0.f, n);
    }

    // ---- projections (6 GEMMs) ----
    sgemm(h_a, Wk + 0 * 16384, bk + 0 * HID, nullptr, k0, M, HID, HID, 0, 0);
    sgemm(h_a, Wq + 0 * 16384, bq + 0 * HID, nullptr, q0, M, HID, HID, 0, 0);
    sgemm(h_a, Wv + 0 * 16384, bv + 0 * HID, nullptr, v0, M, HID, HID, 0, 0);
    sgemm(h_b, Wk + 1 * 16384, bk + 1 * HID, nullptr, k1, M, HID, HID, 0, 0);
    sgemm(h_b, Wq + 1 * 16384, bq + 1 * HID, nullptr, q1, M, HID, HID, 0, 0);
    sgemm(h_b, Wv + 1 * 16384, bv + 1 * HID, nullptr, v1, M, HID, HID, 0, 0);

    // ---- relations: r0 a->b, r1 b->a, r2 a->a ----
    const float* relK[3] = { k0, k1, k0 };
    const float* relV[3] = { v0, v1, v0 };
    const float* relQ[3] = { q1, q0, q0 };
    float* relT[3] = { t1, t0, t0 };
    for (int r = 0; r < 3; r++) {
        int E = Ec[r];
        const int* si = gidx + (size_t)(2 * r) * En;
        const int* di = gidx + (size_t)(2 * r + 1) * En;
        int nh = M * NH;
        fill_u32<<<(nh + 255) / 256, 256>>>(Mx, 0x007FFFFFu, nh);  // enc(-inf)
        fill_f32<<<(nh + 255) / 256, 256>>>(Z, 0.f, nh);
        head_transform_kernel<<<(M + 15) / 16, 256>>>(relK[r], ratt + r * NH * DKv * DKv, kp, M);
        head_transform_kernel<<<(M + 15) / 16, 256>>>(relV[r], rmsg + r * NH * DKv * DKv, vp, M);
        score_kernel<<<(E + 7) / 8, 256>>>(relQ[r], kp, si, di, pri + r * NH, S, Mx, E);
        expz_kernel<<<(E * NH + 255) / 256, 256>>>(S, Mx, Z, di, E);
        agg_kernel<<<(E + 7) / 8, 256>>>(vp, S, Z, si, di, relT[r], E);
    }

    // ---- per-type update: relu(t)@Wa + h -> LN -> FFN ----
    const float* hIn[2] = { h_a, h_b };
    float* tIn[2] = { t0, t1 };
    for (int t = 0; t < 2; t++) {
        sgemm(tIn[t], Wa + (size_t)t * 16384, ba + t * HID, hIn[t], X, M, HID, HID, 1, 0);
        ln_kernel<<<(M + 7) / 8, 256>>>(X, gam + t * HID, bet + t * HID, M);
        sgemm(X, W1 + (size_t)t * 65536, b1 + t * DFFv, nullptr, FF, M, HID, DFFv, 0, 1);
        sgemm(FF, W2 + (size_t)t * 65536, b2 + t * HID, nullptr, out + (size_t)t * M * HID, M, DFFv, HID, 0, 0);
    }
}

// round 3
// speedup vs baseline: 1.7654x; 1.7654x over previous
#include <cuda_runtime.h>
#include <cstdint>
#include <cstddef>

#define Nn 100000
#define En 500000
#define HID 128
#define NH 8
#define DKv 16
#define DFFv 512

// ---------------- scratch (device globals; allocation-free) ----------------
__device__ float g_k[2][(size_t)Nn * HID];
__device__ float g_q[2][(size_t)Nn * HID];
__device__ float g_v[2][(size_t)Nn * HID];
__device__ float g_kp[(size_t)Nn * HID];
__device__ float g_vp[(size_t)Nn * HID];
__device__ float g_s[(size_t)En * NH];
__device__ unsigned g_m[(size_t)Nn * NH];
__device__ float g_z[(size_t)Nn * NH];
__device__ float g_t[2][(size_t)Nn * HID];
__device__ float g_x[(size_t)Nn * HID];
__device__ float g_ff[(size_t)Nn * DFFv];
__device__ int g_idx[6][En];
__device__ int g_is64;

// ---------------- helpers ----------------
__device__ __forceinline__ unsigned fenc(float x) {
    unsigned u = __float_as_uint(x);
    return (u >> 31) ? ~u : (u | 0x80000000u);
}
__device__ __forceinline__ float fdec(unsigned v) {
    return __uint_as_float((v >> 31) ? (v & 0x7fffffffu) : ~v);
}
__device__ __forceinline__ uint32_t f2tf32(float x) {
    uint32_t u;
    asm("cvt.rna.tf32.f32 %0, %1;" : "=r"(u) : "f"(x));
    return u;
}

__global__ void fill_f32(float* p, float v, int n) {
    int i = blockIdx.x * blockDim.x + threadIdx.x;
    if (i < n) p[i] = v;
}
__global__ void fill_u32(unsigned* p, unsigned v, int n) {
    int i = blockIdx.x * blockDim.x + threadIdx.x;
    if (i < n) p[i] = v;
}

// Detect whether index buffers are int64 (odd 32-bit words == 0) or int32.
__global__ void detect_kernel(const unsigned* __restrict__ p) {
    if (blockIdx.x == 0 && threadIdx.x == 0) {
        int any = 0;
        for (int i = 1; i < 2048; i += 2) any |= (p[i] != 0u);
        g_is64 = !any;
    }
}
__global__ void conv_idx_kernel(const void* __restrict__ in, int which, int n) {
    int i = blockIdx.x * blockDim.x + threadIdx.x;
    if (i >= n) return;
    int v = g_is64 ? (int)((const long long*)in)[i] : ((const int*)in)[i];
    g_idx[which][i] = v;
}

// ---------------- TF32 tensor-core GEMM ----------------
// C[M,Nc] = act( (reluA?relu(A):A)[M,K] @ B[K,Nc] + bias (+ res) )
// block tile 128x128, BK=32, 8 warps (2x4), warp tile 64x32, mma.m16n8k8.tf32
#define LDA 36
#define LDB 136
__global__ __launch_bounds__(256) void tf32gemm_kernel(
    const float* __restrict__ A, const float* __restrict__ B,
    const float* __restrict__ bias, const float* __restrict__ res,
    float* __restrict__ C, int M, int K, int Nc, int reluA, int reluOut)
{
    __shared__ uint32_t As[128 * LDA];   // 18.4 KB
    __shared__ uint32_t Bs[32 * LDB];    // 17.4 KB
    int tid = threadIdx.x;
    int warp = tid >> 5, lane = tid & 31;
    int g = lane >> 2, t = lane & 3;
    int wm = warp >> 2, wn = warp & 3;       // 2 x 4 warps
    int rowTile = blockIdx.y * 128;
    int colTile = blockIdx.x * 128;

    float c[4][4][4];
#pragma unroll
    for (int m = 0; m < 4; m++)
#pragma unroll
        for (int n = 0; n < 4; n++)
#pragma unroll
            for (int r = 0; r < 4; r++) c[m][n][r] = 0.f;

    int arow = tid >> 3;          // 0..31
    int acol4 = (tid & 7) * 4;    // 0..28
    int brow = tid >> 3;          // 0..31
    int bcol4 = (tid & 7) * 4;    // 0..28 (x4 passes of +32)

    for (int k0 = 0; k0 < K; k0 += 32) {
        // stage A tile [128 x 32] with tf32 conversion
#pragma unroll
        for (int p = 0; p < 4; p++) {
            int r = arow + 32 * p;
            int gr = rowTile + r;
            float4 v = make_float4(0.f, 0.f, 0.f, 0.f);
            if (gr < M) v = *reinterpret_cast<const float4*>(A + (size_t)gr * K + k0 + acol4);
            if (reluA) {
                v.x = fmaxf(v.x, 0.f); v.y = fmaxf(v.y, 0.f);
                v.z = fmaxf(v.z, 0.f); v.w = fmaxf(v.w, 0.f);
            }
            uint32_t* s = &As[r * LDA + acol4];
            s[0] = f2tf32(v.x); s[1] = f2tf32(v.y);
            s[2] = f2tf32(v.z); s[3] = f2tf32(v.w);
        }
        // stage B tile [32 x 128]
#pragma unroll
        for (int p = 0; p < 4; p++) {
            int cc = bcol4 + 32 * p;
            float4 v = *reinterpret_cast<const float4*>(B + (size_t)(k0 + brow) * Nc + colTile + cc);
            uint32_t* s = &Bs[brow * LDB + cc];
            s[0] = f2tf32(v.x); s[1] = f2tf32(v.y);
            s[2] = f2tf32(v.z); s[3] = f2tf32(v.w);
        }
        __syncthreads();

#pragma unroll
        for (int ks = 0; ks < 32; ks += 8) {
            uint32_t a[4][4], b[4][2];
#pragma unroll
            for (int m = 0; m < 4; m++) {
                int r = wm * 64 + m * 16 + g;
                a[m][0] = As[r * LDA + ks + t];
                a[m][1] = As[(r + 8) * LDA + ks + t];
                a[m][2] = As[r * LDA + ks + t + 4];
                a[m][3] = As[(r + 8) * LDA + ks + t + 4];
            }
#pragma unroll
            for (int n = 0; n < 4; n++) {
                int cc = wn * 32 + n * 8 + g;
                b[n][0] = Bs[(ks + t) * LDB + cc];
                b[n][1] = Bs[(ks + t + 4) * LDB + cc];
            }
#pragma unroll
            for (int m = 0; m < 4; m++)
#pragma unroll
                for (int n = 0; n < 4; n++) {
                    asm volatile(
                        "mma.sync.aligned.m16n8k8.row.col.f32.tf32.tf32.f32 "
                        "{%0,%1,%2,%3}, {%4,%5,%6,%7}, {%8,%9}, {%0,%1,%2,%3};"
                        : "+f"(c[m][n][0]), "+f"(c[m][n][1]),
                          "+f"(c[m][n][2]), "+f"(c[m][n][3])
                        : "r"(a[m][0]), "r"(a[m][1]), "r"(a[m][2]), "r"(a[m][3]),
                          "r"(b[n][0]), "r"(b[n][1]));
                }
        }
        __syncthreads();
    }

    // epilogue
#pragma unroll
    for (int m = 0; m < 4; m++) {
        int row0 = rowTile + wm * 64 + m * 16 + g;
#pragma unroll
        for (int n = 0; n < 4; n++) {
            int col = colTile + wn * 32 + n * 8 + 2 * t;
            float b0 = bias[col], b1 = bias[col + 1];
#pragma unroll
            for (int h = 0; h < 2; h++) {
                int row = row0 + 8 * h;
                if (row >= M) continue;
                size_t off = (size_t)row * Nc + col;
                float v0 = c[m][n][2 * h + 0] + b0;
                float v1 = c[m][n][2 * h + 1] + b1;
                if (res) { v0 += res[off]; v1 += res[off + 1]; }
                if (reluOut) { v0 = fmaxf(v0, 0.f); v1 = fmaxf(v1, 0.f); }
                *reinterpret_cast<float2*>(C + off) = make_float2(v0, v1);
            }
        }
    }
}

// ---------------- per-head 16x16 transform: Y[n,h,:] = X[n,h,:] @ A[h] ----------------
__global__ __launch_bounds__(256) void head_transform_kernel(
    const float* __restrict__ X, const float* __restrict__ A8,
    float* __restrict__ Y, int M)
{
    __shared__ float sA[NH * DKv * DKv];   // 2048
    __shared__ float sX[16 * HID];         // 2048
    int tid = threadIdx.x;
    for (int i = tid; i < NH * DKv * DKv; i += 256) sA[i] = A8[i];
    int base = blockIdx.x * 16;
    for (int i = tid; i < 16 * HID; i += 256) {
        int node = base + (i >> 7);
        sX[i] = (node < M) ? X[(size_t)node * HID + (i & 127)] : 0.f;
    }
    __syncthreads();
#pragma unroll
    for (int o = tid; o < 16 * HID; o += 256) {
        int nl = o >> 7;
        int c = o & 127;
        int h = c >> 4;
        int j = c & 15;
        const float* xr = &sX[nl * HID + h * DKv];
        const float* ar = &sA[h * DKv * DKv + j];
        float acc = 0.f;
#pragma unroll
        for (int i2 = 0; i2 < DKv; i2++) acc += xr[i2] * ar[i2 * DKv];
        int node = base + nl;
        if (node < M) Y[(size_t)node * HID + c] = acc;
    }
}

// ---------------- edge score + segment max ----------------
__global__ __launch_bounds__(256) void score_kernel(
    const float* __restrict__ Q, const float* __restrict__ KP,
    const int* __restrict__ src, const int* __restrict__ dst,
    const float* __restrict__ pri, float* __restrict__ S,
    unsigned* __restrict__ Mx, int Ecnt)
{
    int warp = (blockIdx.x * blockDim.x + threadIdx.x) >> 5;
    int lane = threadIdx.x & 31;
    if (warp >= Ecnt) return;
    int s = src[warp], d = dst[warp];
    float4 qv = *reinterpret_cast<const float4*>(Q + (size_t)d * HID + lane * 4);
    float4 kv = *reinterpret_cast<const float4*>(KP + (size_t)s * HID + lane * 4);
    float p = qv.x * kv.x + qv.y * kv.y + qv.z * kv.z + qv.w * kv.w;
    p += __shfl_xor_sync(0xffffffffu, p, 1);
    p += __shfl_xor_sync(0xffffffffu, p, 2);
    int h = lane >> 2;
    float sc = p * pri[h] * 0.25f;   // / sqrt(DK=16)
    if ((lane & 3) == 0) {
        S[(size_t)warp * NH + h] = sc;
        atomicMax(&Mx[(size_t)d * NH + h], fenc(sc));
    }
}

// ---------------- exp + segment sum ----------------
__global__ __launch_bounds__(256) void expz_kernel(
    float* __restrict__ S, const unsigned* __restrict__ Mx,
    float* __restrict__ Z, const int* __restrict__ dst, int Ecnt)
{
    int idx = blockIdx.x * blockDim.x + threadIdx.x;
    if (idx >= Ecnt * NH) return;
    int e = idx >> 3;
    int h = idx & 7;
    int d = dst[e];
    float m = fdec(Mx[(size_t)d * NH + h]);
    float ev = expf(S[idx] - m);
    S[idx] = ev;
    atomicAdd(&Z[(size_t)d * NH + h], ev);
}

// ---------------- weighted scatter aggregation ----------------
__global__ __launch_bounds__(256) void agg_kernel(
    const float* __restrict__ VP, const float* __restrict__ S,
    const float* __restrict__ Z, const int* __restrict__ src,
    const int* __restrict__ dst, float* __restrict__ T, int Ecnt)
{
    int warp = (blockIdx.x * blockDim.x + threadIdx.x) >> 5;
    int lane = threadIdx.x & 31;
    if (warp >= Ecnt) return;
    int s = src[warp], d = dst[warp];
    int h = lane >> 2;
    float a = S[(size_t)warp * NH + h] / Z[(size_t)d * NH + h];
    float4 v = *reinterpret_cast<const float4*>(VP + (size_t)s * HID + lane * 4);
    float* tp = T + (size_t)d * HID + lane * 4;
    atomicAdd(tp + 0, v.x * a);
    atomicAdd(tp + 1, v.y * a);
    atomicAdd(tp + 2, v.z * a);
    atomicAdd(tp + 3, v.w * a);
}

// ---------------- LayerNorm over 128 (warp per row, in-place) ----------------
__global__ __launch_bounds__(256) void ln_kernel(
    float* __restrict__ X, const float* __restrict__ gamma,
    const float* __restrict__ beta, int M)
{
    int warp = (blockIdx.x * blockDim.x + threadIdx.x) >> 5;
    int lane = threadIdx.x & 31;
    if (warp >= M) return;
    float4 v = *reinterpret_cast<float4*>(X + (size_t)warp * HID + lane * 4);
    float sum = v.x + v.y + v.z + v.w;
    float sq = v.x * v.x + v.y * v.y + v.z * v.z + v.w * v.w;
#pragma unroll
    for (int o = 16; o > 0; o >>= 1) {
        sum += __shfl_xor_sync(0xffffffffu, sum, o);
        sq += __shfl_xor_sync(0xffffffffu, sq, o);
    }
    float mu = sum * (1.f / 128.f);
    float var = sq * (1.f / 128.f) - mu * mu;
    float inv = rsqrtf(var + 1e-5f);
    float4 g = *reinterpret_cast<const float4*>(gamma + lane * 4);
    float4 b = *reinterpret_cast<const float4*>(beta + lane * 4);
    v.x = (v.x - mu) * inv * g.x + b.x;
    v.y = (v.y - mu) * inv * g.y + b.y;
    v.z = (v.z - mu) * inv * g.z + b.z;
    v.w = (v.w - mu) * inv * g.w + b.w;
    *reinterpret_cast<float4*>(X + (size_t)warp * HID + lane * 4) = v;
}

// ---------------- host ----------------
static void sgemm(const float* A, const float* B, const float* bias, const float* res,
                  float* C, int M, int K, int Nc, int reluA, int reluOut)
{
    dim3 grid(Nc / 128, (M + 127) / 128);
    tf32gemm_kernel<<<grid, 256>>>(A, B, bias, res, C, M, K, Nc, reluA, reluOut);
}

template <typename T>
static T* symaddr(const void* sym) {
    void* p = nullptr;
    cudaGetSymbolAddress(&p, sym);
    return (T*)p;
}

extern "C" void kernel_launch(void* const* d_in, const int* in_sizes, int n_in,
                              void* d_out, int out_size)
{
    const float* h_a  = (const float*)d_in[0];
    const float* h_b  = (const float*)d_in[1];
    const float* Wk   = (const float*)d_in[2];
    const float* bk   = (const float*)d_in[3];
    const float* Wq   = (const float*)d_in[4];
    const float* bq   = (const float*)d_in[5];
    const float* Wv   = (const float*)d_in[6];
    const float* bv   = (const float*)d_in[7];
    const float* Wa   = (const float*)d_in[8];
    const float* ba   = (const float*)d_in[9];
    const float* gam  = (const float*)d_in[10];
    const float* bet  = (const float*)d_in[11];
    const float* W1   = (const float*)d_in[12];
    const float* b1   = (const float*)d_in[13];
    const float* W2   = (const float*)d_in[14];
    const float* b2   = (const float*)d_in[15];
    const float* pri  = (const float*)d_in[16];
    const float* ratt = (const float*)d_in[17];
    const float* rmsg = (const float*)d_in[18];

    int M = in_sizes[0] / HID;      // N nodes per type
    int Ec[3] = { in_sizes[19], in_sizes[21], in_sizes[23] };
    float* out = (float*)d_out;

    float* k0 = symaddr<float>(&g_k);  float* k1 = k0 + (size_t)Nn * HID;
    float* q0 = symaddr<float>(&g_q);  float* q1 = q0 + (size_t)Nn * HID;
    float* v0 = symaddr<float>(&g_v);  float* v1 = v0 + (size_t)Nn * HID;
    float* kp = symaddr<float>(&g_kp);
    float* vp = symaddr<float>(&g_vp);
    float* S  = symaddr<float>(&g_s);
    unsigned* Mx = symaddr<unsigned>(&g_m);
    float* Z  = symaddr<float>(&g_z);
    float* t0 = symaddr<float>(&g_t);  float* t1 = t0 + (size_t)Nn * HID;
    float* X  = symaddr<float>(&g_x);
    float* FF = symaddr<float>(&g_ff);
    int* gidx = symaddr<int>(&g_idx);

    // ---- index dtype normalization (device-side detection) ----
    detect_kernel<<<1, 32>>>((const unsigned*)d_in[19]);
    for (int i = 0; i < 6; i++) {
        int e = Ec[i / 2];
        conv_idx_kernel<<<(e + 255) / 256, 256>>>(d_in[19 + i], i, e);
    }

    // ---- zero aggregation targets ----
    {
        int n = 2 * Nn * HID;
        fill_f32<<<(n + 255) / 256, 256>>>(t0, 0.f, n);
    }

    // ---- projections (6 GEMMs) ----
    sgemm(h_a, Wk + 0 * 16384, bk + 0 * HID, nullptr, k0, M, HID, HID, 0, 0);
    sgemm(h_a, Wq + 0 * 16384, bq + 0 * HID, nullptr, q0, M, HID, HID, 0, 0);
    sgemm(h_a, Wv + 0 * 16384, bv + 0 * HID, nullptr, v0, M, HID, HID, 0, 0);
    sgemm(h_b, Wk + 1 * 16384, bk + 1 * HID, nullptr, k1, M, HID, HID, 0, 0);
    sgemm(h_b, Wq + 1 * 16384, bq + 1 * HID, nullptr, q1, M, HID, HID, 0, 0);
    sgemm(h_b, Wv + 1 * 16384, bv + 1 * HID, nullptr, v1, M, HID, HID, 0, 0);

    // ---- relations: r0 a->b, r1 b->a, r2 a->a ----
    const float* relK[3] = { k0, k1, k0 };
    const float* relV[3] = { v0, v1, v0 };
    const float* relQ[3] = { q1, q0, q0 };
    float* relT[3] = { t1, t0, t0 };
    for (int r = 0; r < 3; r++) {
        int E = Ec[r];
        const int* si = gidx + (size_t)(2 * r) * En;
        const int* di = gidx + (size_t)(2 * r + 1) * En;
        int nh = M * NH;
        fill_u32<<<(nh + 255) / 256, 256>>>(Mx, 0x007FFFFFu, nh);  // enc(-inf)
        fill_f32<<<(nh + 255) / 256, 256>>>(Z, 0.f, nh);
        head_transform_kernel<<<(M + 15) / 16, 256>>>(relK[r], ratt + r * NH * DKv * DKv, kp, M);
        head_transform_kernel<<<(M + 15) / 16, 256>>>(relV[r], rmsg + r * NH * DKv * DKv, vp, M);
        score_kernel<<<(E + 7) / 8, 256>>>(relQ[r], kp, si, di, pri + r * NH, S, Mx, E);
        expz_kernel<<<(E * NH + 255) / 256, 256>>>(S, Mx, Z, di, E);
        agg_kernel<<<(E + 7) / 8, 256>>>(vp, S, Z, si, di, relT[r], E);
    }

    // ---- per-type update: relu(t)@Wa + h -> LN -> FFN ----
    const float* hIn[2] = { h_a, h_b };
    float* tIn[2] = { t0, t1 };
    for (int t = 0; t < 2; t++) {
        sgemm(tIn[t], Wa + (size_t)t * 16384, ba + t * HID, hIn[t], X, M, HID, HID, 1, 0);
        ln_kernel<<<(M + 7) / 8, 256>>>(X, gam + t * HID, bet + t * HID, M);
        sgemm(X, W1 + (size_t)t * 65536, b1 + t * DFFv, nullptr, FF, M, HID, DFFv, 0, 1);
        sgemm(FF, W2 + (size_t)t * 65536, b2 + t * HID, nullptr, out + (size_t)t * M * HID, M, DFFv, HID, 0, 0);
    }
}

// round 5
// speedup vs baseline: 2.1892x; 1.2400x over previous
#include <cuda_runtime.h>
#include <cstdint>
#include <cstddef>

#define Nn 100000
#define En 500000
#define HID 128
#define NH 8
#define DKv 16
#define DFFv 512
#define WA_COLS 640
#define WB_COLS 384

// ---------------- scratch (device globals; allocation-free) ----------------
__device__ float g_nodeA[(size_t)Nn * WA_COLS];   // q | kp_r0 | vp_r0 | kp_r2 | vp_r2
__device__ float g_nodeB[(size_t)Nn * WB_COLS];   // q | kp_r1 | vp_r1
__device__ float g_s[(size_t)En * NH];
__device__ float g_t[2][(size_t)Nn * HID];
__device__ float g_x[(size_t)Nn * HID];
__device__ float g_ff[(size_t)Nn * DFFv];
__device__ int g_idx[6][En];
__device__ int g_cnt[Nn];
__device__ int g_off[Nn + 1];
__device__ int g_off2[Nn];
__device__ int g_csr[En];
__device__ float g_wA[(HID + 1) * WA_COLS];       // row 128 = bias
__device__ float g_wB[(HID + 1) * WB_COLS];
__device__ int g_is64;

// ---------------- helpers ----------------
__device__ __forceinline__ uint32_t f2tf32(float x) {
    uint32_t u;
    asm("cvt.rna.tf32.f32 %0, %1;" : "=r"(u) : "f"(x));
    return u;
}

__global__ void fill_i32(int* p, int v, int n) {
    int i = blockIdx.x * blockDim.x + threadIdx.x;
    if (i < n) p[i] = v;
}

// Detect whether index buffers are int64 (odd 32-bit words == 0) or int32.
__global__ void detect_kernel(const unsigned* __restrict__ p) {
    if (blockIdx.x == 0 && threadIdx.x == 0) {
        int any = 0;
        for (int i = 1; i < 2048; i += 2) any |= (p[i] != 0u);
        g_is64 = !any;
    }
}
__global__ void conv_idx_kernel(const void* __restrict__ in, int which, int n) {
    int i = blockIdx.x * blockDim.x + threadIdx.x;
    if (i >= n) return;
    int v = g_is64 ? (int)((const long long*)in)[i] : ((const int*)in)[i];
    g_idx[which][i] = v;
}

// ---------------- weight fusion prep ----------------
// Fold per-relation 16x16 head transforms into the projection weights.
// Layout A (type a): [q | kp_r0 | vp_r0 | kp_r2 | vp_r2], B (type b): [q | kp_r1 | vp_r1]
__global__ void build_weights_kernel(
    const float* __restrict__ Wk, const float* __restrict__ bk,
    const float* __restrict__ Wq, const float* __restrict__ bq,
    const float* __restrict__ Wv, const float* __restrict__ bv,
    const float* __restrict__ att, const float* __restrict__ msg)
{
    int idx = blockIdx.x * blockDim.x + threadIdx.x;
    int total = (HID + 1) * (WA_COLS + WB_COLS);
    if (idx >= total) return;
    int isB = idx >= (HID + 1) * WA_COLS;
    int rem = isB ? idx - (HID + 1) * WA_COLS : idx;
    int cols = isB ? WB_COLS : WA_COLS;
    int i = rem / cols;          // 0..128 (128 = bias row)
    int c = rem % cols;
    int seg = c >> 7;
    int cl = c & 127;
    int h = cl >> 4, j = cl & 15;
    int ty = isB ? 1 : 0;
    float out;
    if (seg == 0) {
        // q passthrough
        out = (i < HID) ? Wq[((size_t)ty * HID + i) * HID + cl] : bq[ty * HID + cl];
    } else {
        // kp/vp: fold 16x16 transform
        int r = isB ? 1 : (seg <= 2 ? 0 : 2);
        int isV = (seg & 1) == 0;   // seg 2,4 -> vp ; seg 1,3 -> kp
        const float* W = isV ? Wv : Wk;
        const float* bb = isV ? bv : bk;
        const float* T = isV ? msg : att;
        const float* Th = T + ((size_t)(r * NH + h) * DKv) * DKv + j;  // T[r][h][l][j]
        float acc = 0.f;
        if (i < HID) {
            const float* Wr = W + ((size_t)ty * HID + i) * HID + h * DKv;
#pragma unroll
            for (int l = 0; l < DKv; l++) acc += Wr[l] * Th[(size_t)l * DKv];
        } else {
            const float* br = bb + ty * HID + h * DKv;
#pragma unroll
            for (int l = 0; l < DKv; l++) acc += br[l] * Th[(size_t)l * DKv];
        }
        out = acc;
    }
    if (isB) g_wB[(size_t)i * WB_COLS + c] = out;
    else     g_wA[(size_t)i * WA_COLS + c] = out;
}

// ---------------- TF32 tensor-core GEMM ----------------
// C[M,Nc] = act( (reluA?relu(A):A)[M,K] @ B[K,Nc] + bias (+ res) )
#define LDA 36
#define LDB 136
__global__ __launch_bounds__(256) void tf32gemm_kernel(
    const float* __restrict__ A, const float* __restrict__ B,
    const float* __restrict__ bias, const float* __restrict__ res,
    float* __restrict__ C, int M, int K, int Nc, int reluA, int reluOut)
{
    __shared__ uint32_t As[128 * LDA];
    __shared__ uint32_t Bs[32 * LDB];
    int tid = threadIdx.x;
    int warp = tid >> 5, lane = tid & 31;
    int g = lane >> 2, t = lane & 3;
    int wm = warp >> 2, wn = warp & 3;
    int rowTile = blockIdx.y * 128;
    int colTile = blockIdx.x * 128;

    float c[4][4][4];
#pragma unroll
    for (int m = 0; m < 4; m++)
#pragma unroll
        for (int n = 0; n < 4; n++)
#pragma unroll
            for (int r = 0; r < 4; r++) c[m][n][r] = 0.f;

    int arow = tid >> 3;
    int acol4 = (tid & 7) * 4;
    int brow = tid >> 3;
    int bcol4 = (tid & 7) * 4;

    for (int k0 = 0; k0 < K; k0 += 32) {
#pragma unroll
        for (int p = 0; p < 4; p++) {
            int r = arow + 32 * p;
            int gr = rowTile + r;
            float4 v = make_float4(0.f, 0.f, 0.f, 0.f);
            if (gr < M) v = *reinterpret_cast<const float4*>(A + (size_t)gr * K + k0 + acol4);
            if (reluA) {
                v.x = fmaxf(v.x, 0.f); v.y = fmaxf(v.y, 0.f);
                v.z = fmaxf(v.z, 0.f); v.w = fmaxf(v.w, 0.f);
            }
            uint32_t* s = &As[r * LDA + acol4];
            s[0] = f2tf32(v.x); s[1] = f2tf32(v.y);
            s[2] = f2tf32(v.z); s[3] = f2tf32(v.w);
        }
#pragma unroll
        for (int p = 0; p < 4; p++) {
            int cc = bcol4 + 32 * p;
            float4 v = *reinterpret_cast<const float4*>(B + (size_t)(k0 + brow) * Nc + colTile + cc);
            uint32_t* s = &Bs[brow * LDB + cc];
            s[0] = f2tf32(v.x); s[1] = f2tf32(v.y);
            s[2] = f2tf32(v.z); s[3] = f2tf32(v.w);
        }
        __syncthreads();

#pragma unroll
        for (int ks = 0; ks < 32; ks += 8) {
            uint32_t a[4][4], b[4][2];
#pragma unroll
            for (int m = 0; m < 4; m++) {
                int r = wm * 64 + m * 16 + g;
                a[m][0] = As[r * LDA + ks + t];
                a[m][1] = As[(r + 8) * LDA + ks + t];
                a[m][2] = As[r * LDA + ks + t + 4];
                a[m][3] = As[(r + 8) * LDA + ks + t + 4];
            }
#pragma unroll
            for (int n = 0; n < 4; n++) {
                int cc = wn * 32 + n * 8 + g;
                b[n][0] = Bs[(ks + t) * LDB + cc];
                b[n][1] = Bs[(ks + t + 4) * LDB + cc];
            }
#pragma unroll
            for (int m = 0; m < 4; m++)
#pragma unroll
                for (int n = 0; n < 4; n++) {
                    asm volatile(
                        "mma.sync.aligned.m16n8k8.row.col.f32.tf32.tf32.f32 "
                        "{%0,%1,%2,%3}, {%4,%5,%6,%7}, {%8,%9}, {%0,%1,%2,%3};"
                        : "+f"(c[m][n][0]), "+f"(c[m][n][1]),
                          "+f"(c[m][n][2]), "+f"(c[m][n][3])
                        : "r"(a[m][0]), "r"(a[m][1]), "r"(a[m][2]), "r"(a[m][3]),
                          "r"(b[n][0]), "r"(b[n][1]));
                }
        }
        __syncthreads();
    }

#pragma unroll
    for (int m = 0; m < 4; m++) {
        int row0 = rowTile + wm * 64 + m * 16 + g;
#pragma unroll
        for (int n = 0; n < 4; n++) {
            int col = colTile + wn * 32 + n * 8 + 2 * t;
            float b0 = bias[col], b1 = bias[col + 1];
#pragma unroll
            for (int h = 0; h < 2; h++) {
                int row = row0 + 8 * h;
                if (row >= M) continue;
                size_t off = (size_t)row * Nc + col;
                float v0 = c[m][n][2 * h + 0] + b0;
                float v1 = c[m][n][2 * h + 1] + b1;
                if (res) { v0 += res[off]; v1 += res[off + 1]; }
                if (reluOut) { v0 = fmaxf(v0, 0.f); v1 = fmaxf(v1, 0.f); }
                *reinterpret_cast<float2*>(C + off) = make_float2(v0, v1);
            }
        }
    }
}

// ---------------- CSR build ----------------
__global__ void hist_kernel(const int* __restrict__ dst, int* __restrict__ cnt, int E) {
    int i = blockIdx.x * blockDim.x + threadIdx.x;
    if (i < E) atomicAdd(&cnt[dst[i]], 1);
}

// single-block exclusive scan of cnt[Nv] -> off[Nv+1] and off2 copy
__global__ __launch_bounds__(1024) void scan_kernel(
    const int* __restrict__ cnt, int* __restrict__ off, int* __restrict__ off2,
    int Nv, int Etot)
{
    __shared__ int part[1024];
    int tid = threadIdx.x;
    int CH = (Nv + 1023) >> 10;
    int lo = tid * CH, hi = min(lo + CH, Nv);
    int s = 0;
    for (int i = lo; i < hi; i++) s += cnt[i];
    part[tid] = s;
    __syncthreads();
    for (int d = 1; d < 1024; d <<= 1) {
        int v = (tid >= d) ? part[tid - d] : 0;
        __syncthreads();
        part[tid] += v;
        __syncthreads();
    }
    int run = (tid == 0) ? 0 : part[tid - 1];
    for (int i = lo; i < hi; i++) {
        off[i] = run;
        off2[i] = run;
        run += cnt[i];
    }
    if (tid == 1023) off[Nv] = Etot;
}

__global__ void scatter_kernel(const int* __restrict__ src, const int* __restrict__ dst,
                               int* __restrict__ off2, int* __restrict__ csr, int E) {
    int i = blockIdx.x * blockDim.x + threadIdx.x;
    if (i >= E) return;
    int pos = atomicAdd(&off2[dst[i]], 1);
    csr[pos] = src[i];
}

// ---------------- fused node attention (gather form, no atomics) ----------------
// warp per dst node: online softmax over incoming edges, then weighted aggregation
__global__ __launch_bounds__(256) void node_attn_kernel(
    const float* __restrict__ SRC, int srcStride, int kpOff, int vpOff,
    const float* __restrict__ DSTQ, int dstStride,
    const int* __restrict__ off, const int* __restrict__ csr,
    const float* __restrict__ pri, float* __restrict__ S,
    float* __restrict__ T, int accumulate, int Nv)
{
    int node = (blockIdx.x * blockDim.x + threadIdx.x) >> 5;
    int lane = threadIdx.x & 31;
    if (node >= Nv) return;
    int h = lane >> 2;
    float prih = pri[h] * 0.25f;   // / sqrt(DK=16)

    float4 q = *reinterpret_cast<const float4*>(DSTQ + (size_t)node * dstStride + lane * 4);
    int s0 = off[node], s1 = off[node + 1];

    float m = -3.4e38f, z = 0.f;
    for (int slot = s0; slot < s1; slot++) {
        int s = csr[slot];
        float4 k = *reinterpret_cast<const float4*>(SRC + (size_t)s * srcStride + kpOff + lane * 4);
        float p = q.x * k.x + q.y * k.y + q.z * k.z + q.w * k.w;
        p += __shfl_xor_sync(0xffffffffu, p, 1);
        p += __shfl_xor_sync(0xffffffffu, p, 2);
        float sc = p * prih;
        S[(size_t)slot * NH + h] = sc;   // all 4 lanes of quad write same value/addr
        float mn = fmaxf(m, sc);
        z = z * __expf(m - mn) + __expf(sc - mn);
        m = mn;
    }
    float inv = (z > 0.f) ? (1.f / z) : 0.f;

    float4 acc = make_float4(0.f, 0.f, 0.f, 0.f);
    for (int slot = s0; slot < s1; slot++) {
        int s = csr[slot];
        float a = __expf(S[(size_t)slot * NH + h] - m) * inv;
        float4 v = *reinterpret_cast<const float4*>(SRC + (size_t)s * srcStride + vpOff + lane * 4);
        acc.x += v.x * a; acc.y += v.y * a;
        acc.z += v.z * a; acc.w += v.w * a;
    }
    float* tp = T + (size_t)node * HID + lane * 4;
    if (accumulate) {
        float4 prev = *reinterpret_cast<float4*>(tp);
        acc.x += prev.x; acc.y += prev.y; acc.z += prev.z; acc.w += prev.w;
    }
    *reinterpret_cast<float4*>(tp) = acc;
}

// ---------------- LayerNorm over 128 (warp per row, in-place) ----------------
__global__ __launch_bounds__(256) void ln_kernel(
    float* __restrict__ X, const float* __restrict__ gamma,
    const float* __restrict__ beta, int M)
{
    int warp = (blockIdx.x * blockDim.x + threadIdx.x) >> 5;
    int lane = threadIdx.x & 31;
    if (warp >= M) return;
    float4 v = *reinterpret_cast<float4*>(X + (size_t)warp * HID + lane * 4);
    float sum = v.x + v.y + v.z + v.w;
    float sq = v.x * v.x + v.y * v.y + v.z * v.z + v.w * v.w;
#pragma unroll
    for (int o = 16; o > 0; o >>= 1) {
        sum += __shfl_xor_sync(0xffffffffu, sum, o);
        sq += __shfl_xor_sync(0xffffffffu, sq, o);
    }
    float mu = sum * (1.f / 128.f);
    float var = sq * (1.f / 128.f) - mu * mu;
    float inv = rsqrtf(var + 1e-5f);
    float4 g = *reinterpret_cast<const float4*>(gamma + lane * 4);
    float4 b = *reinterpret_cast<const float4*>(beta + lane * 4);
    v.x = (v.x - mu) * inv * g.x + b.x;
    v.y = (v.y - mu) * inv * g.y + b.y;
    v.z = (v.z - mu) * inv * g.z + b.z;
    v.w = (v.w - mu) * inv * g.w + b.w;
    *reinterpret_cast<float4*>(X + (size_t)warp * HID + lane * 4) = v;
}

// ---------------- host ----------------
static void sgemm(const float* A, const float* B, const float* bias, const float* res,
                  float* C, int M, int K, int Nc, int reluA, int reluOut)
{
    dim3 grid(Nc / 128, (M + 127) / 128);
    tf32gemm_kernel<<<grid, 256>>>(A, B, bias, res, C, M, K, Nc, reluA, reluOut);
}

template <typename T>
static T* symaddr(const void* sym) {
    void* p = nullptr;
    cudaGetSymbolAddress(&p, sym);
    return (T*)p;
}

extern "C" void kernel_launch(void* const* d_in, const int* in_sizes, int n_in,
                              void* d_out, int out_size)
{
    const float* h_a  = (const float*)d_in[0];
    const float* h_b  = (const float*)d_in[1];
    const float* Wk   = (const float*)d_in[2];
    const float* bk   = (const float*)d_in[3];
    const float* Wq   = (const float*)d_in[4];
    const float* bq   = (const float*)d_in[5];
    const float* Wv   = (const float*)d_in[6];
    const float* bv   = (const float*)d_in[7];
    const float* Wa   = (const float*)d_in[8];
    const float* ba   = (const float*)d_in[9];
    const float* gam  = (const float*)d_in[10];
    const float* bet  = (const float*)d_in[11];
    const float* W1   = (const float*)d_in[12];
    const float* b1   = (const float*)d_in[13];
    const float* W2   = (const float*)d_in[14];
    const float* b2   = (const float*)d_in[15];
    const float* pri  = (const float*)d_in[16];
    const float* ratt = (const float*)d_in[17];
    const float* rmsg = (const float*)d_in[18];

    int M = in_sizes[0] / HID;
    int Ec[3] = { in_sizes[19], in_sizes[21], in_sizes[23] };
    float* out = (float*)d_out;

    float* nodeA = symaddr<float>(&g_nodeA);
    float* nodeB = symaddr<float>(&g_nodeB);
    float* S  = symaddr<float>(&g_s);
    float* t0 = symaddr<float>(&g_t);  float* t1 = t0 + (size_t)Nn * HID;
    float* X  = symaddr<float>(&g_x);
    float* FF = symaddr<float>(&g_ff);
    int* gidx = symaddr<int>(&g_idx);
    int* cnt  = symaddr<int>(&g_cnt);
    int* off  = symaddr<int>(&g_off);
    int* off2 = symaddr<int>(&g_off2);
    int* csr  = symaddr<int>(&g_csr);
    float* wA = symaddr<float>(&g_wA);
    float* wB = symaddr<float>(&g_wB);

    // ---- index dtype normalization ----
    detect_kernel<<<1, 32>>>((const unsigned*)d_in[19]);
    for (int i = 0; i < 6; i++) {
        int e = Ec[i / 2];
        conv_idx_kernel<<<(e + 255) / 256, 256>>>(d_in[19 + i], i, e);
    }

    // ---- fused weight build + 2 wide projection GEMMs ----
    {
        int total = (HID + 1) * (WA_COLS + WB_COLS);
        build_weights_kernel<<<(total + 255) / 256, 256>>>(Wk, bk, Wq, bq, Wv, bv, ratt, rmsg);
    }
    sgemm(h_a, wA, wA + (size_t)HID * WA_COLS, nullptr, nodeA, M, HID, WA_COLS, 0, 0);
    sgemm(h_b, wB, wB + (size_t)HID * WB_COLS, nullptr, nodeB, M, HID, WB_COLS, 0, 0);

    // ---- relations: r0 a->b (out t1), r1 b->a (out t0), r2 a->a (acc into t0) ----
    struct RelCfg {
        const float* src; int srcStride, kpOff, vpOff;
        const float* dq; int dqStride;
        float* outT; int acc;
    };
    RelCfg cfg[3] = {
        { nodeA, WA_COLS, 128, 256, nodeB, WB_COLS, t1, 0 },
        { nodeB, WB_COLS, 128, 256, nodeA, WA_COLS, t0, 0 },
        { nodeA, WA_COLS, 384, 512, nodeA, WA_COLS, t0, 1 },
    };
    for (int r = 0; r < 3; r++) {
        int E = Ec[r];
        const int* si = gidx + (size_t)(2 * r) * En;
        const int* di = gidx + (size_t)(2 * r + 1) * En;
        fill_i32<<<(Nn + 255) / 256, 256>>>(cnt, 0, Nn);
        hist_kernel<<<(E + 255) / 256, 256>>>(di, cnt, E);
        scan_kernel<<<1, 1024>>>(cnt, off, off2, M, E);
        scatter_kernel<<<(E + 255) / 256, 256>>>(si, di, off2, csr, E);
        node_attn_kernel<<<(M * 32 + 255) / 256, 256>>>(
            cfg[r].src, cfg[r].srcStride, cfg[r].kpOff, cfg[r].vpOff,
            cfg[r].dq, cfg[r].dqStride, off, csr, pri + r * NH, S,
            cfg[r].outT, cfg[r].acc, M);
    }

    // ---- per-type update: relu(t)@Wa + h -> LN -> FFN ----
    const float* hIn[2] = { h_a, h_b };
    float* tIn[2] = { t0, t1 };
    for (int t = 0; t < 2; t++) {
        sgemm(tIn[t], Wa + (size_t)t * 16384, ba + t * HID, hIn[t], X, M, HID, HID, 1, 0);
        ln_kernel<<<(M + 7) / 8, 256>>>(X, gam + t * HID, bet + t * HID, M);
        sgemm(X, W1 + (size_t)t * 65536, b1 + t * DFFv, nullptr, FF, M, HID, DFFv, 0, 1);
        sgemm(FF, W2 + (size_t)t * 65536, b2 + t * HID, nullptr, out + (size_t)t * M * HID, M, DFFv, HID, 0, 0);
    }
}

// round 6
// speedup vs baseline: 2.2588x; 1.0318x over previous
#include <cuda_runtime.h>
#include <cstdint>
#include <cstddef>

#define Nn 100000
#define En 500000
#define HID 128
#define NH 8
#define DKv 16
#define DFFv 512
#define WA_COLS 640
#define WB_COLS 384

// ---------------- scratch (device globals; allocation-free) ----------------
__device__ float g_qA[(size_t)Nn * HID];
__device__ float g_qB[(size_t)Nn * HID];
__device__ float g_kp[3][(size_t)Nn * HID];
__device__ float g_vp[3][(size_t)Nn * HID];
__device__ float g_s[(size_t)En * NH];
__device__ float g_t[2][(size_t)Nn * HID];
__device__ float g_x[(size_t)Nn * HID];
__device__ float g_ff[(size_t)Nn * DFFv];
__device__ int g_idx[6][En];
__device__ int g_cnt[Nn];
__device__ int g_off[3][Nn + 1];
__device__ int g_off2[3][Nn];
__device__ int g_csr[3][En];
__device__ float g_wA[(HID + 1) * WA_COLS];       // row 128 = bias
__device__ float g_wB[(HID + 1) * WB_COLS];
__device__ int g_is64;

struct OutSegs { float* p[5]; };

// ---------------- helpers ----------------
__device__ __forceinline__ uint32_t f2tf32(float x) {
    uint32_t u;
    asm("cvt.rna.tf32.f32 %0, %1;" : "=r"(u) : "f"(x));
    return u;
}

__global__ void fill_i32(int* p, int v, int n) {
    int i = blockIdx.x * blockDim.x + threadIdx.x;
    if (i < n) p[i] = v;
}

// Detect whether index buffers are int64 (odd 32-bit words == 0) or int32.
__global__ void detect_kernel(const unsigned* __restrict__ p) {
    if (blockIdx.x == 0 && threadIdx.x == 0) {
        int any = 0;
        for (int i = 1; i < 2048; i += 2) any |= (p[i] != 0u);
        g_is64 = !any;
    }
}
__global__ void conv_idx_kernel(const void* __restrict__ in, int which, int n) {
    int i = blockIdx.x * blockDim.x + threadIdx.x;
    if (i >= n) return;
    int v = g_is64 ? (int)((const long long*)in)[i] : ((const int*)in)[i];
    g_idx[which][i] = v;
}

// ---------------- weight fusion prep ----------------
// Fold per-relation 16x16 head transforms into the projection weights.
// Layout A (type a): [q | kp_r0 | vp_r0 | kp_r2 | vp_r2], B (type b): [q | kp_r1 | vp_r1]
__global__ void build_weights_kernel(
    const float* __restrict__ Wk, const float* __restrict__ bk,
    const float* __restrict__ Wq, const float* __restrict__ bq,
    const float* __restrict__ Wv, const float* __restrict__ bv,
    const float* __restrict__ att, const float* __restrict__ msg)
{
    int idx = blockIdx.x * blockDim.x + threadIdx.x;
    int total = (HID + 1) * (WA_COLS + WB_COLS);
    if (idx >= total) return;
    int isB = idx >= (HID + 1) * WA_COLS;
    int rem = isB ? idx - (HID + 1) * WA_COLS : idx;
    int cols = isB ? WB_COLS : WA_COLS;
    int i = rem / cols;          // 0..128 (128 = bias row)
    int c = rem % cols;
    int seg = c >> 7;
    int cl = c & 127;
    int h = cl >> 4, j = cl & 15;
    int ty = isB ? 1 : 0;
    float out;
    if (seg == 0) {
        out = (i < HID) ? Wq[((size_t)ty * HID + i) * HID + cl] : bq[ty * HID + cl];
    } else {
        int r = isB ? 1 : (seg <= 2 ? 0 : 2);
        int isV = (seg & 1) == 0;   // seg 2,4 -> vp ; seg 1,3 -> kp
        const float* W = isV ? Wv : Wk;
        const float* bb = isV ? bv : bk;
        const float* T = isV ? msg : att;
        const float* Th = T + ((size_t)(r * NH + h) * DKv) * DKv + j;  // T[r][h][l][j]
        float acc = 0.f;
        if (i < HID) {
            const float* Wr = W + ((size_t)ty * HID + i) * HID + h * DKv;
#pragma unroll
            for (int l = 0; l < DKv; l++) acc += Wr[l] * Th[(size_t)l * DKv];
        } else {
            const float* br = bb + ty * HID + h * DKv;
#pragma unroll
            for (int l = 0; l < DKv; l++) acc += br[l] * Th[(size_t)l * DKv];
        }
        out = acc;
    }
    if (isB) g_wB[(size_t)i * WB_COLS + c] = out;
    else     g_wA[(size_t)i * WA_COLS + c] = out;
}

// ---------------- TF32 tensor-core GEMM ----------------
// per-column-tile output bases: tile bx writes segs.p[bx] with row stride segStride
#define LDA 36
#define LDB 136
__global__ __launch_bounds__(256) void tf32gemm_kernel(
    const float* __restrict__ A, const float* __restrict__ B,
    const float* __restrict__ bias, const float* __restrict__ res,
    OutSegs segs, int segStride, int M, int K, int Nc, int reluA, int reluOut)
{
    __shared__ uint32_t As[128 * LDA];
    __shared__ uint32_t Bs[32 * LDB];
    int tid = threadIdx.x;
    int warp = tid >> 5, lane = tid & 31;
    int g = lane >> 2, t = lane & 3;
    int wm = warp >> 2, wn = warp & 3;
    int rowTile = blockIdx.y * 128;
    int colTile = blockIdx.x * 128;
    float* Cb = segs.p[blockIdx.x];

    float c[4][4][4];
#pragma unroll
    for (int m = 0; m < 4; m++)
#pragma unroll
        for (int n = 0; n < 4; n++)
#pragma unroll
            for (int r = 0; r < 4; r++) c[m][n][r] = 0.f;

    int arow = tid >> 3;
    int acol4 = (tid & 7) * 4;
    int brow = tid >> 3;
    int bcol4 = (tid & 7) * 4;

    for (int k0 = 0; k0 < K; k0 += 32) {
#pragma unroll
        for (int p = 0; p < 4; p++) {
            int r = arow + 32 * p;
            int gr = rowTile + r;
            float4 v = make_float4(0.f, 0.f, 0.f, 0.f);
            if (gr < M) v = *reinterpret_cast<const float4*>(A + (size_t)gr * K + k0 + acol4);
            if (reluA) {
                v.x = fmaxf(v.x, 0.f); v.y = fmaxf(v.y, 0.f);
                v.z = fmaxf(v.z, 0.f); v.w = fmaxf(v.w, 0.f);
            }
            uint32_t* s = &As[r * LDA + acol4];
            s[0] = f2tf32(v.x); s[1] = f2tf32(v.y);
            s[2] = f2tf32(v.z); s[3] = f2tf32(v.w);
        }
#pragma unroll
        for (int p = 0; p < 4; p++) {
            int cc = bcol4 + 32 * p;
            float4 v = *reinterpret_cast<const float4*>(B + (size_t)(k0 + brow) * Nc + colTile + cc);
            uint32_t* s = &Bs[brow * LDB + cc];
            s[0] = f2tf32(v.x); s[1] = f2tf32(v.y);
            s[2] = f2tf32(v.z); s[3] = f2tf32(v.w);
        }
        __syncthreads();

#pragma unroll
        for (int ks = 0; ks < 32; ks += 8) {
            uint32_t a[4][4], b[4][2];
#pragma unroll
            for (int m = 0; m < 4; m++) {
                int r = wm * 64 + m * 16 + g;
                a[m][0] = As[r * LDA + ks + t];
                a[m][1] = As[(r + 8) * LDA + ks + t];
                a[m][2] = As[r * LDA + ks + t + 4];
                a[m][3] = As[(r + 8) * LDA + ks + t + 4];
            }
#pragma unroll
            for (int n = 0; n < 4; n++) {
                int cc = wn * 32 + n * 8 + g;
                b[n][0] = Bs[(ks + t) * LDB + cc];
                b[n][1] = Bs[(ks + t + 4) * LDB + cc];
            }
#pragma unroll
            for (int m = 0; m < 4; m++)
#pragma unroll
                for (int n = 0; n < 4; n++) {
                    asm volatile(
                        "mma.sync.aligned.m16n8k8.row.col.f32.tf32.tf32.f32 "
                        "{%0,%1,%2,%3}, {%4,%5,%6,%7}, {%8,%9}, {%0,%1,%2,%3};"
                        : "+f"(c[m][n][0]), "+f"(c[m][n][1]),
                          "+f"(c[m][n][2]), "+f"(c[m][n][3])
                        : "r"(a[m][0]), "r"(a[m][1]), "r"(a[m][2]), "r"(a[m][3]),
                          "r"(b[n][0]), "r"(b[n][1]));
                }
        }
        __syncthreads();
    }

#pragma unroll
    for (int m = 0; m < 4; m++) {
        int row0 = rowTile + wm * 64 + m * 16 + g;
#pragma unroll
        for (int n = 0; n < 4; n++) {
            int cws = wn * 32 + n * 8 + 2 * t;      // col within tile
            int col = colTile + cws;                // global col (bias index)
            float b0 = bias[col], b1 = bias[col + 1];
#pragma unroll
            for (int h = 0; h < 2; h++) {
                int row = row0 + 8 * h;
                if (row >= M) continue;
                size_t off = (size_t)row * segStride + cws;
                float v0 = c[m][n][2 * h + 0] + b0;
                float v1 = c[m][n][2 * h + 1] + b1;
                if (res) { v0 += res[off]; v1 += res[off + 1]; }   // only when segStride==HID
                if (reluOut) { v0 = fmaxf(v0, 0.f); v1 = fmaxf(v1, 0.f); }
                *reinterpret_cast<float2*>(Cb + off) = make_float2(v0, v1);
            }
        }
    }
}

// ---------------- CSR build ----------------
__global__ void hist_kernel(const int* __restrict__ dst, int* __restrict__ cnt, int E) {
    int i = blockIdx.x * blockDim.x + threadIdx.x;
    if (i < E) atomicAdd(&cnt[dst[i]], 1);
}

__global__ __launch_bounds__(1024) void scan_kernel(
    const int* __restrict__ cnt, int* __restrict__ off, int* __restrict__ off2,
    int Nv, int Etot)
{
    __shared__ int part[1024];
    int tid = threadIdx.x;
    int CH = (Nv + 1023) >> 10;
    int lo = tid * CH, hi = min(lo + CH, Nv);
    int s = 0;
    for (int i = lo; i < hi; i++) s += cnt[i];
    part[tid] = s;
    __syncthreads();
    for (int d = 1; d < 1024; d <<= 1) {
        int v = (tid >= d) ? part[tid - d] : 0;
        __syncthreads();
        part[tid] += v;
        __syncthreads();
    }
    int run = (tid == 0) ? 0 : part[tid - 1];
    for (int i = lo; i < hi; i++) {
        off[i] = run;
        off2[i] = run;
        run += cnt[i];
    }
    if (tid == 1023) off[Nv] = Etot;
}

__global__ void scatter_kernel(const int* __restrict__ src, const int* __restrict__ dst,
                               int* __restrict__ off2, int* __restrict__ csr, int E) {
    int i = blockIdx.x * blockDim.x + threadIdx.x;
    if (i >= E) return;
    int pos = atomicAdd(&off2[dst[i]], 1);
    csr[pos] = src[i];
}

// ---------------- fused node attention (gather form, dense L2-resident arrays) ----------------
__global__ __launch_bounds__(256) void node_attn_kernel(
    const float* __restrict__ KP, const float* __restrict__ VP,
    const float* __restrict__ Q,
    const int* __restrict__ off, const int* __restrict__ csr,
    const float* __restrict__ pri, float* __restrict__ S,
    float* __restrict__ T, int accumulate, int Nv)
{
    int node = (blockIdx.x * blockDim.x + threadIdx.x) >> 5;
    int lane = threadIdx.x & 31;
    if (node >= Nv) return;
    int h = lane >> 2;
    float prih = pri[h] * 0.25f;   // / sqrt(DK=16)

    float4 q = *reinterpret_cast<const float4*>(Q + (size_t)node * HID + lane * 4);
    int s0 = off[node], s1 = off[node + 1];

    float m = -3.4e38f, z = 0.f;
    for (int slot = s0; slot < s1; slot++) {
        int s = csr[slot];
        float4 k = *reinterpret_cast<const float4*>(KP + (size_t)s * HID + lane * 4);
        float p = q.x * k.x + q.y * k.y + q.z * k.z + q.w * k.w;
        p += __shfl_xor_sync(0xffffffffu, p, 1);
        p += __shfl_xor_sync(0xffffffffu, p, 2);
        float sc = p * prih;
        S[(size_t)slot * NH + h] = sc;   // quad lanes write same value/addr (benign)
        float mn = fmaxf(m, sc);
        z = z * __expf(m - mn) + __expf(sc - mn);
        m = mn;
    }
    float inv = (z > 0.f) ? (1.f / z) : 0.f;

    float4 acc = make_float4(0.f, 0.f, 0.f, 0.f);
    for (int slot = s0; slot < s1; slot++) {
        int s = csr[slot];
        float a = __expf(S[(size_t)slot * NH + h] - m) * inv;
        float4 v = *reinterpret_cast<const float4*>(VP + (size_t)s * HID + lane * 4);
        acc.x += v.x * a; acc.y += v.y * a;
        acc.z += v.z * a; acc.w += v.w * a;
    }
    float* tp = T + (size_t)node * HID + lane * 4;
    if (accumulate) {
        float4 prev = *reinterpret_cast<float4*>(tp);
        acc.x += prev.x; acc.y += prev.y; acc.z += prev.z; acc.w += prev.w;
    }
    *reinterpret_cast<float4*>(tp) = acc;
}

// ---------------- LayerNorm over 128 (warp per row, in-place) ----------------
__global__ __launch_bounds__(256) void ln_kernel(
    float* __restrict__ X, const float* __restrict__ gamma,
    const float* __restrict__ beta, int M)
{
    int warp = (blockIdx.x * blockDim.x + threadIdx.x) >> 5;
    int lane = threadIdx.x & 31;
    if (warp >= M) return;
    float4 v = *reinterpret_cast<float4*>(X + (size_t)warp * HID + lane * 4);
    float sum = v.x + v.y + v.z + v.w;
    float sq = v.x * v.x + v.y * v.y + v.z * v.z + v.w * v.w;
#pragma unroll
    for (int o = 16; o > 0; o >>= 1) {
        sum += __shfl_xor_sync(0xffffffffu, sum, o);
        sq += __shfl_xor_sync(0xffffffffu, sq, o);
    }
    float mu = sum * (1.f / 128.f);
    float var = sq * (1.f / 128.f) - mu * mu;
    float inv = rsqrtf(var + 1e-5f);
    float4 g = *reinterpret_cast<const float4*>(gamma + lane * 4);
    float4 b = *reinterpret_cast<const float4*>(beta + lane * 4);
    v.x = (v.x - mu) * inv * g.x + b.x;
    v.y = (v.y - mu) * inv * g.y + b.y;
    v.z = (v.z - mu) * inv * g.z + b.z;
    v.w = (v.w - mu) * inv * g.w + b.w;
    *reinterpret_cast<float4*>(X + (size_t)warp * HID + lane * 4) = v;
}

// ---------------- host ----------------
static void sgemm_seg(const float* A, const float* B, const float* bias, const float* res,
                      OutSegs segs, int segStride, int M, int K, int Nc,
                      int reluA, int reluOut, cudaStream_t st)
{
    dim3 grid(Nc / 128, (M + 127) / 128);
    tf32gemm_kernel<<<grid, 256, 0, st>>>(A, B, bias, res, segs, segStride, M, K, Nc, reluA, reluOut);
}

template <typename T>
static T* symaddr(const void* sym) {
    void* p = nullptr;
    cudaGetSymbolAddress(&p, sym);
    return (T*)p;
}

extern "C" void kernel_launch(void* const* d_in, const int* in_sizes, int n_in,
                              void* d_out, int out_size)
{
    const float* h_a  = (const float*)d_in[0];
    const float* h_b  = (const float*)d_in[1];
    const float* Wk   = (const float*)d_in[2];
    const float* bk   = (const float*)d_in[3];
    const float* Wq   = (const float*)d_in[4];
    const float* bq   = (const float*)d_in[5];
    const float* Wv   = (const float*)d_in[6];
    const float* bv   = (const float*)d_in[7];
    const float* Wa   = (const float*)d_in[8];
    const float* ba   = (const float*)d_in[9];
    const float* gam  = (const float*)d_in[10];
    const float* bet  = (const float*)d_in[11];
    const float* W1   = (const float*)d_in[12];
    const float* b1   = (const float*)d_in[13];
    const float* W2   = (const float*)d_in[14];
    const float* b2   = (const float*)d_in[15];
    const float* pri  = (const float*)d_in[16];
    const float* ratt = (const float*)d_in[17];
    const float* rmsg = (const float*)d_in[18];

    int M = in_sizes[0] / HID;
    int Ec[3] = { in_sizes[19], in_sizes[21], in_sizes[23] };
    float* out = (float*)d_out;

    float* qA = symaddr<float>(&g_qA);
    float* qB = symaddr<float>(&g_qB);
    float* kpB = symaddr<float>(&g_kp);   // [3] arrays
    float* vpB = symaddr<float>(&g_vp);
    float* kp[3] = { kpB, kpB + (size_t)Nn * HID, kpB + 2 * (size_t)Nn * HID };
    float* vp[3] = { vpB, vpB + (size_t)Nn * HID, vpB + 2 * (size_t)Nn * HID };
    float* S  = symaddr<float>(&g_s);
    float* t0 = symaddr<float>(&g_t);  float* t1 = t0 + (size_t)Nn * HID;
    float* X  = symaddr<float>(&g_x);
    float* FF = symaddr<float>(&g_ff);
    int* gidx = symaddr<int>(&g_idx);
    int* cnt  = symaddr<int>(&g_cnt);
    int* offB = symaddr<int>(&g_off);
    int* off2B = symaddr<int>(&g_off2);
    int* csrB = symaddr<int>(&g_csr);
    int* off[3]  = { offB, offB + (Nn + 1), offB + 2 * (Nn + 1) };
    int* off2[3] = { off2B, off2B + Nn, off2B + 2 * Nn };
    int* csr[3]  = { csrB, csrB + En, csrB + 2 * En };
    float* wA = symaddr<float>(&g_wA);
    float* wB = symaddr<float>(&g_wB);

    static cudaStream_t s1 = nullptr;
    static cudaEvent_t evF = nullptr, evJ = nullptr;
    if (!s1) {
        cudaStreamCreateWithFlags(&s1, cudaStreamNonBlocking);
        cudaEventCreateWithFlags(&evF, cudaEventDisableTiming);
        cudaEventCreateWithFlags(&evJ, cudaEventDisableTiming);
    }

    // ---- index dtype normalization (default stream) ----
    detect_kernel<<<1, 32>>>((const unsigned*)d_in[19]);
    for (int i = 0; i < 6; i++) {
        int e = Ec[i / 2];
        conv_idx_kernel<<<(e + 255) / 256, 256>>>(d_in[19 + i], i, e);
    }

    // ---- fork: CSR build on side stream, GEMMs on default ----
    cudaEventRecord(evF, 0);
    cudaStreamWaitEvent(s1, evF, 0);
    for (int r = 0; r < 3; r++) {
        int E = Ec[r];
        const int* si = gidx + (size_t)(2 * r) * En;
        const int* di = gidx + (size_t)(2 * r + 1) * En;
        fill_i32<<<(Nn + 255) / 256, 256, 0, s1>>>(cnt, 0, Nn);
        hist_kernel<<<(E + 255) / 256, 256, 0, s1>>>(di, cnt, E);
        scan_kernel<<<1, 1024, 0, s1>>>(cnt, off[r], off2[r], M, E);
        scatter_kernel<<<(E + 255) / 256, 256, 0, s1>>>(si, di, off2[r], csr[r], E);
    }
    cudaEventRecord(evJ, s1);

    // ---- fused weight build + 2 wide projection GEMMs (dense per-segment outputs) ----
    {
        int total = (HID + 1) * (WA_COLS + WB_COLS);
        build_weights_kernel<<<(total + 255) / 256, 256>>>(Wk, bk, Wq, bq, Wv, bv, ratt, rmsg);
    }
    {
        OutSegs sa; sa.p[0] = qA; sa.p[1] = kp[0]; sa.p[2] = vp[0]; sa.p[3] = kp[2]; sa.p[4] = vp[2];
        sgemm_seg(h_a, wA, wA + (size_t)HID * WA_COLS, nullptr, sa, HID, M, HID, WA_COLS, 0, 0, 0);
        OutSegs sb; sb.p[0] = qB; sb.p[1] = kp[1]; sb.p[2] = vp[1]; sb.p[3] = nullptr; sb.p[4] = nullptr;
        sgemm_seg(h_b, wB, wB + (size_t)HID * WB_COLS, nullptr, sb, HID, M, HID, WB_COLS, 0, 0, 0);
    }

    // ---- join, then node attention per relation ----
    cudaStreamWaitEvent(0, evJ, 0);
    const float* relQ[3] = { qB, qA, qA };
    float* relT[3] = { t1, t0, t0 };
    int relAcc[3] = { 0, 0, 1 };
    for (int r = 0; r < 3; r++) {
        node_attn_kernel<<<(M * 32 + 255) / 256, 256>>>(
            kp[r], vp[r], relQ[r], off[r], csr[r], pri + r * NH, S,
            relT[r], relAcc[r], M);
    }

    // ---- per-type update: relu(t)@Wa + h -> LN -> FFN ----
    const float* hIn[2] = { h_a, h_b };
    float* tIn[2] = { t0, t1 };
    for (int t = 0; t < 2; t++) {
        OutSegs sx; sx.p[0] = X; sx.p[1] = sx.p[2] = sx.p[3] = sx.p[4] = nullptr;
        sgemm_seg(tIn[t], Wa + (size_t)t * 16384, ba + t * HID, hIn[t], sx, HID, M, HID, HID, 1, 0, 0);
        ln_kernel<<<(M + 7) / 8, 256>>>(X, gam + t * HID, bet + t * HID, M);
        OutSegs sf; sf.p[0] = FF; sf.p[1] = FF + 128; sf.p[2] = FF + 256; sf.p[3] = FF + 384; sf.p[4] = nullptr;
        sgemm_seg(X, W1 + (size_t)t * 65536, b1 + t * DFFv, nullptr, sf, DFFv, M, HID, DFFv, 0, 1, 0);
        OutSegs so; so.p[0] = out + (size_t)t * M * HID; so.p[1] = so.p[2] = so.p[3] = so.p[4] = nullptr;
        sgemm_seg(FF, W2 + (size_t)t * 65536, b2 + t * HID, nullptr, so, HID, M, DFFv, HID, 0, 0, 0);
    }
}